// round 6
// baseline (speedup 1.0000x reference)
#include <cuda_runtime.h>
#include <cuda_fp16.h>
#include <cuda_bf16.h>
#include <math.h>

#define NN 50000
#define EE 800000
#define FF 128

// ---------------- scratch (static device globals; no allocation) ----------------
__device__ int    g_cnt[NN];
__device__ float  g_dis[NN];
__device__ int    g_rowstart[NN + 1];
__device__ int    g_fillptr[NN];
__device__ int    g_csr[EE];
__device__ int    g_blocksum[256];
__device__ int    g_blockoff[256];
__device__ __half g_bufT[(size_t)NN * FF];    // transformed features (fp16)
__device__ __half g_bufT2[(size_t)NN * FF];   // ping-pong partner

// ---------------- small helpers ----------------
__device__ __forceinline__ float4 ld4(const float* p) { return *(const float4*)p; }

__device__ __forceinline__ unsigned smem_u32(const void* p) {
    unsigned a;
    asm("{ .reg .u64 t; cvta.to.shared.u64 t, %1; cvt.u32.u64 %0, t; }" : "=r"(a) : "l"(p));
    return a;
}
__device__ __forceinline__ void ldsm_x4(unsigned addr, unsigned& r0, unsigned& r1,
                                        unsigned& r2, unsigned& r3) {
    asm volatile("ldmatrix.sync.aligned.m8n8.x4.shared.b16 {%0,%1,%2,%3}, [%4];"
                 : "=r"(r0), "=r"(r1), "=r"(r2), "=r"(r3) : "r"(addr));
}
__device__ __forceinline__ void ldsm_x4t(unsigned addr, unsigned& r0, unsigned& r1,
                                         unsigned& r2, unsigned& r3) {
    asm volatile("ldmatrix.sync.aligned.m8n8.x4.trans.shared.b16 {%0,%1,%2,%3}, [%4];"
                 : "=r"(r0), "=r"(r1), "=r"(r2), "=r"(r3) : "r"(addr));
}
__device__ __forceinline__ void mma16816(float* d, const unsigned* a, const unsigned* b) {
    asm volatile(
        "mma.sync.aligned.m16n8k16.row.col.f32.f16.f16.f32 "
        "{%0,%1,%2,%3},{%4,%5,%6,%7},{%8,%9},{%0,%1,%2,%3};"
        : "+f"(d[0]), "+f"(d[1]), "+f"(d[2]), "+f"(d[3])
        : "r"(a[0]), "r"(a[1]), "r"(a[2]), "r"(a[3]), "r"(b[0]), "r"(b[1]));
}

__device__ __forceinline__ float elu1(float v) { return v > 0.f ? v : expm1f(v); }

__device__ __forceinline__ void gather_row(const __half* __restrict__ T, int row, int lane,
                                           float& fx, float& fy, float& fz, float& fw) {
    uint2 raw = *((const uint2*)(T + (size_t)row * FF) + lane);
    __half2 a = *(__half2*)&raw.x;
    __half2 b = *(__half2*)&raw.y;
    float2 f0 = __half22float2(a);
    float2 f1 = __half22float2(b);
    fx = f0.x; fy = f0.y; fz = f1.x; fw = f1.y;
}

// aggregate one node v into (ax,ay,az,aw) for this lane's 4 features
__device__ __forceinline__ void agg_node(const __half* __restrict__ T, int v, int lane,
                                         float& ax, float& ay, float& az, float& aw) {
    float disv = g_dis[v];
    float wself = disv * disv;
    float tx, tyv, tz, tw;
    gather_row(T, v, lane, tx, tyv, tz, tw);
    ax = tx * wself; ay = tyv * wself; az = tz * wself; aw = tw * wself;

    int beg = g_rowstart[v];
    int end = g_rowstart[v + 1];
    int e = beg;
    for (; e + 4 <= end; e += 4) {
        int s0 = g_csr[e + 0], s1 = g_csr[e + 1], s2 = g_csr[e + 2], s3 = g_csr[e + 3];
        float w0 = g_dis[s0] * disv, w1 = g_dis[s1] * disv;
        float w2 = g_dis[s2] * disv, w3 = g_dis[s3] * disv;
        float x0, y0, z0, q0, x1, y1, z1, q1, x2, y2, z2, q2, x3, y3, z3, q3;
        gather_row(T, s0, lane, x0, y0, z0, q0);
        gather_row(T, s1, lane, x1, y1, z1, q1);
        gather_row(T, s2, lane, x2, y2, z2, q2);
        gather_row(T, s3, lane, x3, y3, z3, q3);
        ax = fmaf(x0, w0, ax); ay = fmaf(y0, w0, ay); az = fmaf(z0, w0, az); aw = fmaf(q0, w0, aw);
        ax = fmaf(x1, w1, ax); ay = fmaf(y1, w1, ay); az = fmaf(z1, w1, az); aw = fmaf(q1, w1, aw);
        ax = fmaf(x2, w2, ax); ay = fmaf(y2, w2, ay); az = fmaf(z2, w2, az); aw = fmaf(q2, w2, aw);
        ax = fmaf(x3, w3, ax); ay = fmaf(y3, w3, ay); az = fmaf(z3, w3, az); aw = fmaf(q3, w3, aw);
    }
    for (; e < end; e++) {
        int s = g_csr[e];
        float w = g_dis[s] * disv;
        float fx, fy, fz, fw;
        gather_row(T, s, lane, fx, fy, fz, fw);
        ax = fmaf(fx, w, ax); ay = fmaf(fy, w, ay); az = fmaf(fz, w, az); aw = fmaf(fw, w, aw);
    }
}

// ---------------- CSR build ----------------
__global__ void zero_cnt_kernel() {
    int i = blockIdx.x * blockDim.x + threadIdx.x;
    if (i < NN) g_cnt[i] = 0;
}

__global__ void count_kernel(const int* __restrict__ dst) {
    int i = blockIdx.x * blockDim.x + threadIdx.x;
    if (i < EE) atomicAdd(&g_cnt[dst[i]], 1);
}

__global__ void dis_kernel() {
    int i = blockIdx.x * blockDim.x + threadIdx.x;
    if (i < NN) g_dis[i] = rsqrtf((float)g_cnt[i] + 1.0f);  // +1 self loop
}

__device__ __forceinline__ int block_exclusive_scan_256(int val, int tid, int* total_out) {
    int lane = tid & 31, w = tid >> 5;
    int x = val;
#pragma unroll
    for (int off = 1; off < 32; off <<= 1) {
        int y = __shfl_up_sync(0xFFFFFFFFu, x, off);
        if (lane >= off) x += y;
    }
    __shared__ int ws[8];
    if (lane == 31) ws[w] = x;
    __syncthreads();
    __shared__ int wo[9];
    if (tid == 0) {
        int run = 0;
#pragma unroll
        for (int i = 0; i < 8; i++) { wo[i] = run; run += ws[i]; }
        wo[8] = run;
    }
    __syncthreads();
    *total_out = wo[8];
    return x - val + wo[w];
}

__global__ void scan1_kernel() {
    int b = blockIdx.x, t = threadIdx.x;
    int i = b * 256 + t;
    int val = (i < NN) ? g_cnt[i] : 0;
    int total;
    int excl = block_exclusive_scan_256(val, t, &total);
    if (i < NN) g_rowstart[i] = excl;
    if (t == 0) g_blocksum[b] = total;
}

__global__ void scan2_kernel() {
    int t = threadIdx.x;
    int nb = (NN + 255) / 256;
    int val = (t < nb) ? g_blocksum[t] : 0;
    int total;
    int excl = block_exclusive_scan_256(val, t, &total);
    g_blockoff[t] = excl;
}

__global__ void scan3_kernel() {
    int b = blockIdx.x, t = threadIdx.x;
    int i = b * 256 + t;
    if (i < NN) {
        int rs = g_rowstart[i] + g_blockoff[b];
        g_rowstart[i] = rs;
        g_fillptr[i]  = rs;
    }
    if (i == 0) g_rowstart[NN] = EE;
}

__global__ void fill_kernel(const int* __restrict__ src, const int* __restrict__ dst) {
    int i = blockIdx.x * blockDim.x + threadIdx.x;
    if (i < EE) {
        int d = dst[i];
        int p = atomicAdd(&g_fillptr[d], 1);
        g_csr[p] = src[i];
    }
}

// ---------------- shared GEMM core pieces ----------------
#define AST 136   // smem half-stride (128 + 8 pad)
#define GEMM_SMEM (2 * 128 * AST * 2)   // As + Bs, bytes

extern __shared__ __align__(16) __half smx[];

// phase-2 HMMA + fp16 epilogue; As/Bs ready, writes C tile at m0
__device__ __forceinline__ void hmma_tile_and_store(__half* As, __half* Bs,
                                                    __half* __restrict__ C,
                                                    int m0, int M, int tid) {
    int warp = tid >> 5, lane = tid & 31;
    int wm = (warp & 3) * 32;
    int wn = (warp >> 2) * 64;

    float d[2][8][4];
#pragma unroll
    for (int i = 0; i < 2; i++)
#pragma unroll
        for (int j = 0; j < 8; j++)
#pragma unroll
            for (int q = 0; q < 4; q++) d[i][j][q] = 0.f;

    int lrow = lane & 15;
    int lcol8 = (lane >> 4) << 3;
    unsigned aoff0 = smem_u32(&As[(wm + lrow) * AST]);
    unsigned aoff1 = smem_u32(&As[(wm + 16 + lrow) * AST]);
    unsigned boff  = smem_u32(&Bs[lrow * AST]);

#pragma unroll
    for (int k0 = 0; k0 < FF; k0 += 16) {
        unsigned a0[4], a1[4];
        ldsm_x4(aoff0 + (k0 + lcol8) * 2, a0[0], a0[1], a0[2], a0[3]);
        ldsm_x4(aoff1 + (k0 + lcol8) * 2, a1[0], a1[1], a1[2], a1[3]);
        unsigned b[4][4];
#pragma unroll
        for (int nj = 0; nj < 4; nj++)
            ldsm_x4t(boff + (k0 * AST + wn + nj * 16 + lcol8) * 2,
                     b[nj][0], b[nj][1], b[nj][2], b[nj][3]);
#pragma unroll
        for (int nj = 0; nj < 4; nj++) {
            mma16816(d[0][2 * nj],     a0, &b[nj][0]);
            mma16816(d[0][2 * nj + 1], a0, &b[nj][2]);
            mma16816(d[1][2 * nj],     a1, &b[nj][0]);
            mma16816(d[1][2 * nj + 1], a1, &b[nj][2]);
        }
    }

    __syncthreads();
    __half* Cs = As;
    int crow = lane >> 2;
    int ccol = (lane & 3) * 2;
#pragma unroll
    for (int mi = 0; mi < 2; mi++) {
#pragma unroll
        for (int jj = 0; jj < 8; jj++) {
            int r = wm + mi * 16 + crow;
            int c = wn + jj * 8 + ccol;
            __half2 lo = __floats2half2_rn(d[mi][jj][0], d[mi][jj][1]);
            __half2 hi = __floats2half2_rn(d[mi][jj][2], d[mi][jj][3]);
            *(__half2*)&Cs[r * AST + c]       = lo;
            *(__half2*)&Cs[(r + 8) * AST + c] = hi;
        }
    }
    __syncthreads();
#pragma unroll
    for (int p = 0; p < 8; p++) {
        int idx = p * 256 + tid;
        int row = idx >> 4, c8 = (idx & 15) * 8;
        int gm = m0 + row;
        if (gm < M)
            *(uint4*)(C + (size_t)gm * FF + c8) = *(uint4*)&Cs[row * AST + c8];
    }
}

// ---------------- layer-0 GEMM: C_half = A_f32 * W ----------------
__global__ __launch_bounds__(256)
void gemm_tc_kernel(const float* __restrict__ A, const float* __restrict__ W,
                    __half* __restrict__ C, int M) {
    __half* As = smx;
    __half* Bs = smx + 128 * AST;
    int tid = threadIdx.x;
    int m0 = blockIdx.x * 128;

#pragma unroll
    for (int p = 0; p < 16; p++) {
        int idx = p * 256 + tid;
        int row = idx >> 5, c4 = (idx & 31) * 4;
        int gm = m0 + row;
        float4 v = (gm < M) ? ld4(A + (size_t)gm * FF + c4) : make_float4(0.f, 0.f, 0.f, 0.f);
        __half2 h0 = __floats2half2_rn(v.x, v.y);
        __half2 h1 = __floats2half2_rn(v.z, v.w);
        *(uint2*)&As[row * AST + c4] = make_uint2(*(unsigned*)&h0, *(unsigned*)&h1);
    }
#pragma unroll
    for (int p = 0; p < 16; p++) {
        int idx = p * 256 + tid;
        int row = idx >> 5, c4 = (idx & 31) * 4;
        float4 v = ld4(W + (size_t)row * FF + c4);
        __half2 h0 = __floats2half2_rn(v.x, v.y);
        __half2 h1 = __floats2half2_rn(v.z, v.w);
        *(uint2*)&Bs[row * AST + c4] = make_uint2(*(unsigned*)&h0, *(unsigned*)&h1);
    }
    __syncthreads();
    hmma_tile_and_store(As, Bs, C, m0, M, tid);
}

// ---------------- fused: agg(T_prev) + bias + ELU -> smem A-tile -> GEMM(W) -> T_next ----------------
__global__ __launch_bounds__(256)
void agg_gemm_kernel(const __half* __restrict__ T, const float* __restrict__ bias,
                     const float* __restrict__ W, __half* __restrict__ C, int M) {
    __half* As = smx;
    __half* Bs = smx + 128 * AST;
    int tid = threadIdx.x;
    int m0 = blockIdx.x * 128;
    int warp = tid >> 5, lane = tid & 31;
    int c = lane * 4;

    // load + convert W tile first (independent of aggregation)
#pragma unroll
    for (int p = 0; p < 16; p++) {
        int idx = p * 256 + tid;
        int row = idx >> 5, c4 = (idx & 31) * 4;
        float4 v = ld4(W + (size_t)row * FF + c4);
        __half2 h0 = __floats2half2_rn(v.x, v.y);
        __half2 h1 = __floats2half2_rn(v.z, v.w);
        *(uint2*)&Bs[row * AST + c4] = make_uint2(*(unsigned*)&h0, *(unsigned*)&h1);
    }

    // phase 1: each warp aggregates 16 nodes; write ELU(agg+b) as fp16 into As
    float4 b = ld4(bias + c);
#pragma unroll 1
    for (int t = 0; t < 16; t++) {
        int row = warp * 16 + t;
        int v = m0 + row;
        float ax = 0.f, ay = 0.f, az = 0.f, aw = 0.f;
        if (v < M) {
            agg_node(T, v, lane, ax, ay, az, aw);
            ax = elu1(ax + b.x); ay = elu1(ay + b.y);
            az = elu1(az + b.z); aw = elu1(aw + b.w);
        }
        __half2 h0 = __floats2half2_rn(ax, ay);
        __half2 h1 = __floats2half2_rn(az, aw);
        *(uint2*)&As[row * AST + c] = make_uint2(*(unsigned*)&h0, *(unsigned*)&h1);
    }
    __syncthreads();

    // phase 2: HMMA + store
    hmma_tile_and_store(As, Bs, C, m0, M, tid);
}

// ---------------- final: agg + bias + ELU + linear head ----------------
__global__ __launch_bounds__(256)
void agg_elu_head_kernel(const __half* __restrict__ T, const float* __restrict__ bias,
                         const float* __restrict__ Wl, const float* __restrict__ bl,
                         float* __restrict__ out) {
    int warp = threadIdx.x >> 5;
    int lane = threadIdx.x & 31;
    int v = blockIdx.x * 8 + warp;
    if (v >= NN) return;
    int c = lane * 4;

    float ax, ay, az, aw;
    agg_node(T, v, lane, ax, ay, az, aw);

    float4 b = ld4(bias + c);
    float4 wl = ld4(Wl + c);
    float s = elu1(ax + b.x) * wl.x + elu1(ay + b.y) * wl.y
            + elu1(az + b.z) * wl.z + elu1(aw + b.w) * wl.w;
#pragma unroll
    for (int off = 16; off > 0; off >>= 1) s += __shfl_down_sync(0xFFFFFFFFu, s, off);
    if (lane == 0) out[v] = s + bl[0];
}

// ---------------- launch ----------------
extern "C" void kernel_launch(void* const* d_in, const int* in_sizes, int n_in,
                              void* d_out, int out_size) {
    const float* x  = (const float*)d_in[0];   // [N,128]
    const float* Ws = (const float*)d_in[1];   // [3,128,128]
    const float* bs = (const float*)d_in[2];   // [3,128]
    const float* Wl = (const float*)d_in[3];   // [128,1]
    const float* bl = (const float*)d_in[4];   // [1]
    const int*   ei = (const int*)d_in[5];     // [2,E]
    const int* src = ei;
    const int* dst = ei + EE;
    float* out = (float*)d_out;

    __half *bufT, *bufT2;
    cudaGetSymbolAddress((void**)&bufT, g_bufT);
    cudaGetSymbolAddress((void**)&bufT2, g_bufT2);

    static cudaStream_t s_side = (cudaStream_t)0;
    static cudaEvent_t  s_fork = nullptr, s_join = nullptr;
    static int s_init = 0;
    if (!s_init) {
        cudaFuncSetAttribute(gemm_tc_kernel,
                             cudaFuncAttributeMaxDynamicSharedMemorySize, GEMM_SMEM);
        cudaFuncSetAttribute(agg_gemm_kernel,
                             cudaFuncAttributeMaxDynamicSharedMemorySize, GEMM_SMEM);
        cudaStream_t tmp;
        if (cudaStreamCreateWithFlags(&tmp, cudaStreamNonBlocking) == cudaSuccess) {
            cudaEvent_t e1, e2;
            if (cudaEventCreateWithFlags(&e1, cudaEventDisableTiming) == cudaSuccess &&
                cudaEventCreateWithFlags(&e2, cudaEventDisableTiming) == cudaSuccess) {
                s_side = tmp; s_fork = e1; s_join = e2;
            }
        }
        s_init = 1;
    }

    int nb = (NN + 255) / 256;            // 196
    int gemm_grid = (NN + 127) / 128;     // 391
    int node_grid = (NN + 7) / 8;

    if (s_side) {
        cudaEventRecord(s_fork, 0);
        cudaStreamWaitEvent(s_side, s_fork, 0);
        zero_cnt_kernel<<<nb, 256, 0, s_side>>>();
        count_kernel<<<(EE + 255) / 256, 256, 0, s_side>>>(dst);
        dis_kernel<<<nb, 256, 0, s_side>>>();
        scan1_kernel<<<nb, 256, 0, s_side>>>();
        scan2_kernel<<<1, 256, 0, s_side>>>();
        scan3_kernel<<<nb, 256, 0, s_side>>>();
        fill_kernel<<<(EE + 255) / 256, 256, 0, s_side>>>(src, dst);
        cudaEventRecord(s_join, s_side);

        gemm_tc_kernel<<<gemm_grid, 256, GEMM_SMEM>>>(x, Ws + 0 * FF * FF, bufT, NN);
        cudaStreamWaitEvent(0, s_join, 0);
    } else {
        zero_cnt_kernel<<<nb, 256>>>();
        count_kernel<<<(EE + 255) / 256, 256>>>(dst);
        dis_kernel<<<nb, 256>>>();
        scan1_kernel<<<nb, 256>>>();
        scan2_kernel<<<1, 256>>>();
        scan3_kernel<<<nb, 256>>>();
        fill_kernel<<<(EE + 255) / 256, 256>>>(src, dst);
        gemm_tc_kernel<<<gemm_grid, 256, GEMM_SMEM>>>(x, Ws + 0 * FF * FF, bufT, NN);
    }

    // layer boundary 0->1: agg(T0)+b0+ELU then GEMM W1  -> T1
    agg_gemm_kernel<<<gemm_grid, 256, GEMM_SMEM>>>(bufT, bs + 0 * FF, Ws + 1 * FF * FF, bufT2, NN);
    // layer boundary 1->2: agg(T1)+b1+ELU then GEMM W2  -> T2
    agg_gemm_kernel<<<gemm_grid, 256, GEMM_SMEM>>>(bufT2, bs + 1 * FF, Ws + 2 * FF * FF, bufT, NN);
    // final: agg(T2)+b2+ELU + head
    agg_elu_head_kernel<<<node_grid, 256>>>(bufT, bs + 2 * FF, Wl, bl, out);
}

// round 7
// speedup vs baseline: 2.3656x; 2.3656x over previous
#include <cuda_runtime.h>
#include <cuda_fp16.h>
#include <cuda_bf16.h>
#include <math.h>

#define NN 50000
#define EE 800000
#define FF 128

// ---------------- scratch (static device globals; no allocation) ----------------
__device__ int    g_cnt[NN];
__device__ float  g_dis[NN];
__device__ int    g_rowstart[NN + 1];
__device__ int    g_fillptr[NN];
__device__ int    g_csr[EE];
__device__ int    g_blocksum[256];
__device__ int    g_blockoff[256];
__device__ __half g_bufT[(size_t)NN * FF];    // transformed features (fp16)
__device__ __half g_bufH[(size_t)NN * FF];    // post-ELU features (fp16)

// ---------------- small helpers ----------------
__device__ __forceinline__ float4 ld4(const float* p) { return *(const float4*)p; }

__device__ __forceinline__ unsigned smem_u32(const void* p) {
    unsigned a;
    asm("{ .reg .u64 t; cvta.to.shared.u64 t, %1; cvt.u32.u64 %0, t; }" : "=r"(a) : "l"(p));
    return a;
}
__device__ __forceinline__ void ldsm_x4(unsigned addr, unsigned& r0, unsigned& r1,
                                        unsigned& r2, unsigned& r3) {
    asm volatile("ldmatrix.sync.aligned.m8n8.x4.shared.b16 {%0,%1,%2,%3}, [%4];"
                 : "=r"(r0), "=r"(r1), "=r"(r2), "=r"(r3) : "r"(addr));
}
__device__ __forceinline__ void ldsm_x4t(unsigned addr, unsigned& r0, unsigned& r1,
                                         unsigned& r2, unsigned& r3) {
    asm volatile("ldmatrix.sync.aligned.m8n8.x4.trans.shared.b16 {%0,%1,%2,%3}, [%4];"
                 : "=r"(r0), "=r"(r1), "=r"(r2), "=r"(r3) : "r"(addr));
}
__device__ __forceinline__ void mma16816(float* d, const unsigned* a, const unsigned* b) {
    asm volatile(
        "mma.sync.aligned.m16n8k16.row.col.f32.f16.f16.f32 "
        "{%0,%1,%2,%3},{%4,%5,%6,%7},{%8,%9},{%0,%1,%2,%3};"
        : "+f"(d[0]), "+f"(d[1]), "+f"(d[2]), "+f"(d[3])
        : "r"(a[0]), "r"(a[1]), "r"(a[2]), "r"(a[3]), "r"(b[0]), "r"(b[1]));
}

__device__ __forceinline__ float elu1(float v) { return v > 0.f ? v : expm1f(v); }

__device__ __forceinline__ void gather_row(const __half* __restrict__ T, int row, int lane,
                                           float& fx, float& fy, float& fz, float& fw) {
    uint2 raw = *((const uint2*)(T + (size_t)row * FF) + lane);
    __half2 a = *(__half2*)&raw.x;
    __half2 b = *(__half2*)&raw.y;
    float2 f0 = __half22float2(a);
    float2 f1 = __half22float2(b);
    fx = f0.x; fy = f0.y; fz = f1.x; fw = f1.y;
}

// aggregate node v: coalesced csr/dis load per 32-edge chunk, shfl broadcast,
// then back-to-back row gathers (no dependent index loads in the inner loop).
__device__ __forceinline__ void agg_node(const __half* __restrict__ T, int v, int lane,
                                         float& ax, float& ay, float& az, float& aw) {
    float disv = g_dis[v];
    float wself = disv * disv;
    float tx, tyv, tz, tw;
    gather_row(T, v, lane, tx, tyv, tz, tw);
    ax = tx * wself; ay = tyv * wself; az = tz * wself; aw = tw * wself;

    int beg = g_rowstart[v];
    int end = g_rowstart[v + 1];
    for (int base = beg; base < end; base += 32) {
        int n = end - base; if (n > 32) n = 32;
        int my_s = 0; float my_w = 0.f;
        if (lane < n) {
            my_s = g_csr[base + lane];
            my_w = g_dis[my_s] * disv;
        }
        int j = 0;
        for (; j + 4 <= n; j += 4) {
            int   s0 = __shfl_sync(0xFFFFFFFFu, my_s, j + 0);
            int   s1 = __shfl_sync(0xFFFFFFFFu, my_s, j + 1);
            int   s2 = __shfl_sync(0xFFFFFFFFu, my_s, j + 2);
            int   s3 = __shfl_sync(0xFFFFFFFFu, my_s, j + 3);
            float w0 = __shfl_sync(0xFFFFFFFFu, my_w, j + 0);
            float w1 = __shfl_sync(0xFFFFFFFFu, my_w, j + 1);
            float w2 = __shfl_sync(0xFFFFFFFFu, my_w, j + 2);
            float w3 = __shfl_sync(0xFFFFFFFFu, my_w, j + 3);
            float x0, y0, z0, q0, x1, y1, z1, q1, x2, y2, z2, q2, x3, y3, z3, q3;
            gather_row(T, s0, lane, x0, y0, z0, q0);
            gather_row(T, s1, lane, x1, y1, z1, q1);
            gather_row(T, s2, lane, x2, y2, z2, q2);
            gather_row(T, s3, lane, x3, y3, z3, q3);
            ax = fmaf(x0, w0, ax); ay = fmaf(y0, w0, ay); az = fmaf(z0, w0, az); aw = fmaf(q0, w0, aw);
            ax = fmaf(x1, w1, ax); ay = fmaf(y1, w1, ay); az = fmaf(z1, w1, az); aw = fmaf(q1, w1, aw);
            ax = fmaf(x2, w2, ax); ay = fmaf(y2, w2, ay); az = fmaf(z2, w2, az); aw = fmaf(q2, w2, aw);
            ax = fmaf(x3, w3, ax); ay = fmaf(y3, w3, ay); az = fmaf(z3, w3, az); aw = fmaf(q3, w3, aw);
        }
        for (; j < n; j++) {
            int   s = __shfl_sync(0xFFFFFFFFu, my_s, j);
            float w = __shfl_sync(0xFFFFFFFFu, my_w, j);
            float fx, fy, fz, fw;
            gather_row(T, s, lane, fx, fy, fz, fw);
            ax = fmaf(fx, w, ax); ay = fmaf(fy, w, ay); az = fmaf(fz, w, az); aw = fmaf(fw, w, aw);
        }
    }
}

// ---------------- CSR build ----------------
__global__ void zero_cnt_kernel() {
    int i = blockIdx.x * blockDim.x + threadIdx.x;
    if (i < NN) g_cnt[i] = 0;
}

__global__ void count_kernel(const int* __restrict__ dst) {
    int i = blockIdx.x * blockDim.x + threadIdx.x;
    if (i < EE) atomicAdd(&g_cnt[dst[i]], 1);
}

__global__ void dis_kernel() {
    int i = blockIdx.x * blockDim.x + threadIdx.x;
    if (i < NN) g_dis[i] = rsqrtf((float)g_cnt[i] + 1.0f);  // +1 self loop
}

__device__ __forceinline__ int block_exclusive_scan_256(int val, int tid, int* total_out) {
    int lane = tid & 31, w = tid >> 5;
    int x = val;
#pragma unroll
    for (int off = 1; off < 32; off <<= 1) {
        int y = __shfl_up_sync(0xFFFFFFFFu, x, off);
        if (lane >= off) x += y;
    }
    __shared__ int ws[8];
    if (lane == 31) ws[w] = x;
    __syncthreads();
    __shared__ int wo[9];
    if (tid == 0) {
        int run = 0;
#pragma unroll
        for (int i = 0; i < 8; i++) { wo[i] = run; run += ws[i]; }
        wo[8] = run;
    }
    __syncthreads();
    *total_out = wo[8];
    return x - val + wo[w];
}

__global__ void scan1_kernel() {
    int b = blockIdx.x, t = threadIdx.x;
    int i = b * 256 + t;
    int val = (i < NN) ? g_cnt[i] : 0;
    int total;
    int excl = block_exclusive_scan_256(val, t, &total);
    if (i < NN) g_rowstart[i] = excl;
    if (t == 0) g_blocksum[b] = total;
}

__global__ void scan2_kernel() {
    int t = threadIdx.x;
    int nb = (NN + 255) / 256;
    int val = (t < nb) ? g_blocksum[t] : 0;
    int total;
    int excl = block_exclusive_scan_256(val, t, &total);
    g_blockoff[t] = excl;
}

__global__ void scan3_kernel() {
    int b = blockIdx.x, t = threadIdx.x;
    int i = b * 256 + t;
    if (i < NN) {
        int rs = g_rowstart[i] + g_blockoff[b];
        g_rowstart[i] = rs;
        g_fillptr[i]  = rs;
    }
    if (i == 0) g_rowstart[NN] = EE;
}

__global__ void fill_kernel(const int* __restrict__ src, const int* __restrict__ dst) {
    int i = blockIdx.x * blockDim.x + threadIdx.x;
    if (i < EE) {
        int d = dst[i];
        int p = atomicAdd(&g_fillptr[d], 1);
        g_csr[p] = src[i];
    }
}

// ---------------- GEMM core ----------------
#define AST 136   // smem half-stride (128 + 8 pad)
#define GEMM_SMEM (2 * 128 * AST * 2)   // As + Bs, bytes

extern __shared__ __align__(16) __half smx[];

__device__ __forceinline__ void load_W_tile(__half* Bs, const float* __restrict__ W, int tid) {
#pragma unroll
    for (int p = 0; p < 16; p++) {
        int idx = p * 256 + tid;
        int row = idx >> 5, c4 = (idx & 31) * 4;
        float4 v = ld4(W + (size_t)row * FF + c4);
        __half2 h0 = __floats2half2_rn(v.x, v.y);
        __half2 h1 = __floats2half2_rn(v.z, v.w);
        *(uint2*)&Bs[row * AST + c4] = make_uint2(*(unsigned*)&h0, *(unsigned*)&h1);
    }
}

__device__ __forceinline__ void hmma_tile_and_store(__half* As, __half* Bs,
                                                    __half* __restrict__ C,
                                                    int m0, int M, int tid) {
    int warp = tid >> 5, lane = tid & 31;
    int wm = (warp & 3) * 32;
    int wn = (warp >> 2) * 64;

    float d[2][8][4];
#pragma unroll
    for (int i = 0; i < 2; i++)
#pragma unroll
        for (int j = 0; j < 8; j++)
#pragma unroll
            for (int q = 0; q < 4; q++) d[i][j][q] = 0.f;

    int lrow = lane & 15;
    int lcol8 = (lane >> 4) << 3;
    unsigned aoff0 = smem_u32(&As[(wm + lrow) * AST]);
    unsigned aoff1 = smem_u32(&As[(wm + 16 + lrow) * AST]);
    unsigned boff  = smem_u32(&Bs[lrow * AST]);

#pragma unroll
    for (int k0 = 0; k0 < FF; k0 += 16) {
        unsigned a0[4], a1[4];
        ldsm_x4(aoff0 + (k0 + lcol8) * 2, a0[0], a0[1], a0[2], a0[3]);
        ldsm_x4(aoff1 + (k0 + lcol8) * 2, a1[0], a1[1], a1[2], a1[3]);
        unsigned b[4][4];
#pragma unroll
        for (int nj = 0; nj < 4; nj++)
            ldsm_x4t(boff + (k0 * AST + wn + nj * 16 + lcol8) * 2,
                     b[nj][0], b[nj][1], b[nj][2], b[nj][3]);
#pragma unroll
        for (int nj = 0; nj < 4; nj++) {
            mma16816(d[0][2 * nj],     a0, &b[nj][0]);
            mma16816(d[0][2 * nj + 1], a0, &b[nj][2]);
            mma16816(d[1][2 * nj],     a1, &b[nj][0]);
            mma16816(d[1][2 * nj + 1], a1, &b[nj][2]);
        }
    }

    __syncthreads();
    __half* Cs = As;
    int crow = lane >> 2;
    int ccol = (lane & 3) * 2;
#pragma unroll
    for (int mi = 0; mi < 2; mi++) {
#pragma unroll
        for (int jj = 0; jj < 8; jj++) {
            int r = wm + mi * 16 + crow;
            int c = wn + jj * 8 + ccol;
            __half2 lo = __floats2half2_rn(d[mi][jj][0], d[mi][jj][1]);
            __half2 hi = __floats2half2_rn(d[mi][jj][2], d[mi][jj][3]);
            *(__half2*)&Cs[r * AST + c]       = lo;
            *(__half2*)&Cs[(r + 8) * AST + c] = hi;
        }
    }
    __syncthreads();
#pragma unroll
    for (int p = 0; p < 8; p++) {
        int idx = p * 256 + tid;
        int row = idx >> 4, c8 = (idx & 15) * 8;
        int gm = m0 + row;
        if (gm < M)
            *(uint4*)(C + (size_t)gm * FF + c8) = *(uint4*)&Cs[row * AST + c8];
    }
}

// layer-0 GEMM: C_half = A_f32 * W
__global__ __launch_bounds__(256)
void gemm_tc_kernel(const float* __restrict__ A, const float* __restrict__ W,
                    __half* __restrict__ C, int M) {
    __half* As = smx;
    __half* Bs = smx + 128 * AST;
    int tid = threadIdx.x;
    int m0 = blockIdx.x * 128;

#pragma unroll
    for (int p = 0; p < 16; p++) {
        int idx = p * 256 + tid;
        int row = idx >> 5, c4 = (idx & 31) * 4;
        int gm = m0 + row;
        float4 v = (gm < M) ? ld4(A + (size_t)gm * FF + c4) : make_float4(0.f, 0.f, 0.f, 0.f);
        __half2 h0 = __floats2half2_rn(v.x, v.y);
        __half2 h1 = __floats2half2_rn(v.z, v.w);
        *(uint2*)&As[row * AST + c4] = make_uint2(*(unsigned*)&h0, *(unsigned*)&h1);
    }
    load_W_tile(Bs, W, tid);
    __syncthreads();
    hmma_tile_and_store(As, Bs, C, m0, M, tid);
}

// layer-1/2 GEMM: C_half = A_half * W   (A already fp16 — straight uint4 copies)
__global__ __launch_bounds__(256)
void gemm_tc_half_kernel(const __half* __restrict__ A, const float* __restrict__ W,
                         __half* __restrict__ C, int M) {
    __half* As = smx;
    __half* Bs = smx + 128 * AST;
    int tid = threadIdx.x;
    int m0 = blockIdx.x * 128;

#pragma unroll
    for (int p = 0; p < 8; p++) {
        int idx = p * 256 + tid;
        int row = idx >> 4, c8 = (idx & 15) * 8;
        int gm = m0 + row;
        uint4 v = (gm < M) ? *(const uint4*)(A + (size_t)gm * FF + c8)
                           : make_uint4(0u, 0u, 0u, 0u);
        *(uint4*)&As[row * AST + c8] = v;
    }
    load_W_tile(Bs, W, tid);
    __syncthreads();
    hmma_tile_and_store(As, Bs, C, m0, M, tid);
}

// ---------------- aggregation + bias + ELU -> fp16 H (warp per node) ----------------
__global__ __launch_bounds__(256)
void agg_elu_kernel(const __half* __restrict__ T, const float* __restrict__ bias,
                    __half* __restrict__ Hout) {
    int warp = threadIdx.x >> 5;
    int lane = threadIdx.x & 31;
    int v = blockIdx.x * 8 + warp;
    if (v >= NN) return;
    int c = lane * 4;

    float ax, ay, az, aw;
    agg_node(T, v, lane, ax, ay, az, aw);

    float4 b = ld4(bias + c);
    __half2 h0 = __floats2half2_rn(elu1(ax + b.x), elu1(ay + b.y));
    __half2 h1 = __floats2half2_rn(elu1(az + b.z), elu1(aw + b.w));
    *((uint2*)(Hout + (size_t)v * FF) + lane) = make_uint2(*(unsigned*)&h0, *(unsigned*)&h1);
}

// final: agg + bias + ELU + linear head
__global__ __launch_bounds__(256)
void agg_elu_head_kernel(const __half* __restrict__ T, const float* __restrict__ bias,
                         const float* __restrict__ Wl, const float* __restrict__ bl,
                         float* __restrict__ out) {
    int warp = threadIdx.x >> 5;
    int lane = threadIdx.x & 31;
    int v = blockIdx.x * 8 + warp;
    if (v >= NN) return;
    int c = lane * 4;

    float ax, ay, az, aw;
    agg_node(T, v, lane, ax, ay, az, aw);

    float4 b = ld4(bias + c);
    float4 wl = ld4(Wl + c);
    float s = elu1(ax + b.x) * wl.x + elu1(ay + b.y) * wl.y
            + elu1(az + b.z) * wl.z + elu1(aw + b.w) * wl.w;
#pragma unroll
    for (int off = 16; off > 0; off >>= 1) s += __shfl_down_sync(0xFFFFFFFFu, s, off);
    if (lane == 0) out[v] = s + bl[0];
}

// ---------------- launch ----------------
extern "C" void kernel_launch(void* const* d_in, const int* in_sizes, int n_in,
                              void* d_out, int out_size) {
    const float* x  = (const float*)d_in[0];   // [N,128]
    const float* Ws = (const float*)d_in[1];   // [3,128,128]
    const float* bs = (const float*)d_in[2];   // [3,128]
    const float* Wl = (const float*)d_in[3];   // [128,1]
    const float* bl = (const float*)d_in[4];   // [1]
    const int*   ei = (const int*)d_in[5];     // [2,E]
    const int* src = ei;
    const int* dst = ei + EE;
    float* out = (float*)d_out;

    __half *bufT, *bufH;
    cudaGetSymbolAddress((void**)&bufT, g_bufT);
    cudaGetSymbolAddress((void**)&bufH, g_bufH);

    static cudaStream_t s_side = (cudaStream_t)0;
    static cudaEvent_t  s_fork = nullptr, s_join = nullptr;
    static int s_init = 0;
    if (!s_init) {
        cudaFuncSetAttribute(gemm_tc_kernel,
                             cudaFuncAttributeMaxDynamicSharedMemorySize, GEMM_SMEM);
        cudaFuncSetAttribute(gemm_tc_half_kernel,
                             cudaFuncAttributeMaxDynamicSharedMemorySize, GEMM_SMEM);
        cudaStream_t tmp;
        if (cudaStreamCreateWithFlags(&tmp, cudaStreamNonBlocking) == cudaSuccess) {
            cudaEvent_t e1, e2;
            if (cudaEventCreateWithFlags(&e1, cudaEventDisableTiming) == cudaSuccess &&
                cudaEventCreateWithFlags(&e2, cudaEventDisableTiming) == cudaSuccess) {
                s_side = tmp; s_fork = e1; s_join = e2;
            }
        }
        s_init = 1;
    }

    int nb = (NN + 255) / 256;            // 196
    int gemm_grid = (NN + 127) / 128;     // 391
    int node_grid = (NN + 7) / 8;

    if (s_side) {
        cudaEventRecord(s_fork, 0);
        cudaStreamWaitEvent(s_side, s_fork, 0);
        zero_cnt_kernel<<<nb, 256, 0, s_side>>>();
        count_kernel<<<(EE + 255) / 256, 256, 0, s_side>>>(dst);
        dis_kernel<<<nb, 256, 0, s_side>>>();
        scan1_kernel<<<nb, 256, 0, s_side>>>();
        scan2_kernel<<<1, 256, 0, s_side>>>();
        scan3_kernel<<<nb, 256, 0, s_side>>>();
        fill_kernel<<<(EE + 255) / 256, 256, 0, s_side>>>(src, dst);
        cudaEventRecord(s_join, s_side);

        gemm_tc_kernel<<<gemm_grid, 256, GEMM_SMEM>>>(x, Ws + 0 * FF * FF, bufT, NN);
        cudaStreamWaitEvent(0, s_join, 0);
    } else {
        zero_cnt_kernel<<<nb, 256>>>();
        count_kernel<<<(EE + 255) / 256, 256>>>(dst);
        dis_kernel<<<nb, 256>>>();
        scan1_kernel<<<nb, 256>>>();
        scan2_kernel<<<1, 256>>>();
        scan3_kernel<<<nb, 256>>>();
        fill_kernel<<<(EE + 255) / 256, 256>>>(src, dst);
        gemm_tc_kernel<<<gemm_grid, 256, GEMM_SMEM>>>(x, Ws + 0 * FF * FF, bufT, NN);
    }

    // layer 0
    agg_elu_kernel<<<node_grid, 256>>>(bufT, bs + 0 * FF, bufH);
    // layer 1
    gemm_tc_half_kernel<<<gemm_grid, 256, GEMM_SMEM>>>(bufH, Ws + 1 * FF * FF, bufT, NN);
    agg_elu_kernel<<<node_grid, 256>>>(bufT, bs + 1 * FF, bufH);
    // layer 2 + fused head
    gemm_tc_half_kernel<<<gemm_grid, 256, GEMM_SMEM>>>(bufH, Ws + 2 * FF * FF, bufT, NN);
    agg_elu_head_kernel<<<node_grid, 256>>>(bufT, bs + 2 * FF, Wl, bl, out);
}